// round 16
// baseline (speedup 1.0000x reference)
#include <cuda_runtime.h>
#include <cuda_bf16.h>
#include <math.h>
#include <stdint.h>

// ---------------------------------------------------------------------------
// PeerRegularizationLayerAtt — mma.sync Gram (2 CTAs/SM, reg-capped) +
// multi-stream overlap + BN stats fused into the MLP GEMM epilogue.
// N=4096 queries, M=16384 peers, C=Cs=256, K=5.
// ---------------------------------------------------------------------------

#define HW     4096
#define NQ     4096
#define NP     16384
#define C1     256
#define F1     128
#define F2     64
#define KNN    5
#define QT     64
#define GSPLIT 8
#define PTILE  64
#define TILES  ((NP / GSPLIT) / PTILE)   // 32
#define SHORT  8
#define NCAND  (GSPLIT * SHORT)          // 64

#if defined(__CUDACC_VER_MAJOR__) && (__CUDACC_VER_MAJOR__ > 12 || \
    (__CUDACC_VER_MAJOR__ == 12 && __CUDACC_VER_MINOR__ >= 4))
#define GRAM_BOUNDS __maxnreg__(104)
#else
#define GRAM_BOUNDS __launch_bounds__(256, 2)
#endif

// ---------------- float scratch layout ----------------
constexpr size_t OFF_Z1Q  = 0;
constexpr size_t OFF_Z2Q  = OFF_Z1Q  + (size_t)F1 * NQ;
constexpr size_t OFF_Z1P  = OFF_Z2Q  + (size_t)F2 * NQ;
constexpr size_t OFF_Z2P  = OFF_Z1P  + (size_t)F1 * NP;
constexpr size_t OFF_PN   = OFF_Z2P  + (size_t)F2 * NP;
constexpr size_t OFF_A1   = OFF_PN   + NP;
constexpr size_t OFF_A2   = OFF_A1   + NQ;
constexpr size_t OFF_AL1Q = OFF_A2   + NP;
constexpr size_t OFF_SH1Q = OFF_AL1Q + F1;
constexpr size_t OFF_AL2Q = OFF_SH1Q + F1;
constexpr size_t OFF_SH2Q = OFF_AL2Q + F2;
constexpr size_t OFF_AL1P = OFF_SH2Q + F2;
constexpr size_t OFF_SH1P = OFF_AL1P + F1;
constexpr size_t OFF_AL2P = OFF_SH1P + F1;
constexpr size_t OFF_SH2P = OFF_AL2P + F2;
constexpr size_t OFF_QT   = OFF_SH2P + F2;
constexpr size_t OFF_PT   = OFF_QT   + (size_t)NQ * C1;
constexpr size_t OFF_W    = OFF_PT   + (size_t)NP * C1;
constexpr size_t OFF_PSP  = OFF_W    + (size_t)NQ * KNN;      // F1*256 partial sums (peers)
constexpr size_t OFF_PQP  = OFF_PSP  + (size_t)F1 * 256;
constexpr size_t OFF_PSQ  = OFF_PQP  + (size_t)F1 * 256;      // F1*64 (query)
constexpr size_t OFF_PQQ  = OFF_PSQ  + (size_t)F1 * 64;
constexpr size_t SCRATCH_FLOATS = OFF_PQQ + (size_t)F1 * 64;

constexpr size_t IOFF_SI  = 0;
constexpr size_t IOFF_WI  = (size_t)NQ * NCAND;
constexpr size_t SCRATCH_INTS = IOFF_WI + (size_t)NQ * KNN;

__device__ float g_scratch[SCRATCH_FLOATS];
__device__ int   g_iscratch[SCRATCH_INTS];
__device__ __nv_bfloat16 g_bf16[(size_t)(NQ + NP) * C1];

// ---------------- PTX helpers (arch-agnostic: ldmatrix + mma.sync) ----------
__device__ __forceinline__ uint32_t s2u(const void* p) {
    uint32_t a;
    asm("{ .reg .u64 t; cvta.to.shared.u64 t, %1; cvt.u32.u64 %0, t; }"
        : "=r"(a) : "l"(p));
    return a;
}
__device__ __forceinline__ void ldsm_x4(uint32_t* r, uint32_t addr) {
    asm volatile("ldmatrix.sync.aligned.m8n8.x4.shared.b16 {%0,%1,%2,%3}, [%4];"
        : "=r"(r[0]), "=r"(r[1]), "=r"(r[2]), "=r"(r[3]) : "r"(addr));
}
__device__ __forceinline__ void mma16816(float* d, const uint32_t* a,
                                         const uint32_t* b) {
    asm volatile(
        "mma.sync.aligned.m16n8k16.row.col.f32.bf16.bf16.f32 "
        "{%0,%1,%2,%3}, {%4,%5,%6,%7}, {%8,%9}, {%0,%1,%2,%3};"
        : "+f"(d[0]), "+f"(d[1]), "+f"(d[2]), "+f"(d[3])
        : "r"(a[0]), "r"(a[1]), "r"(a[2]), "r"(a[3]), "r"(b[0]), "r"(b[1]));
}

// ---------------------------------------------------------------------------
// transpose+convert: X [B][C][HW] fp32 -> Xt [n][c] fp32, Xb [n][c] bf16
// ---------------------------------------------------------------------------
__global__ __launch_bounds__(256) void transconv(
    const float* __restrict__ X, float* __restrict__ Xt, __nv_bfloat16* __restrict__ Xb)
{
    __shared__ float t[32][33];
    const int n0 = blockIdx.x * 32, c0 = blockIdx.y * 32;
    const int tx = threadIdx.x & 31, ty = threadIdx.x >> 5;
    const float* base = X + (size_t)(n0 >> 12) * (C1 * HW) + (n0 & 4095);
#pragma unroll
    for (int i = 0; i < 4; i++) {
        int cc = ty + i * 8;
        t[cc][tx] = base[(size_t)(c0 + cc) * HW + tx];
    }
    __syncthreads();
#pragma unroll
    for (int i = 0; i < 4; i++) {
        int r = ty + i * 8;
        float v = t[tx][r];
        size_t o = (size_t)(n0 + r) * C1 + c0 + tx;
        Xt[o] = v;
        Xb[o] = __float2bfloat16(v);
    }
}

// exact fp32 peer squared norms straight from [B][C][HW] layout (coalesced)
__global__ __launch_bounds__(256) void pnormA(
    const float* __restrict__ PC, float* __restrict__ pn)
{
    const int j = blockIdx.x * 256 + threadIdx.x;
    const float* base = PC + (size_t)(j >> 12) * (C1 * HW) + (j & 4095);
    float s = 0.f;
#pragma unroll 8
    for (int c = 0; c < C1; c++) { float v = base[(size_t)c * HW]; s = fmaf(v, v, s); }
    pn[j] = s;
}

// ---------------------------------------------------------------------------
// mma.sync Gram + per-thread-per-row top-4 (registers) -> top-8/split
// ---------------------------------------------------------------------------
#define SMQ   0
#define SMP   65536
#define SMPN  98304
#define SMTOT (SMPN + 256)

__device__ __forceinline__ void fill_q(char* dst, const __nv_bfloat16* __restrict__ src,
                                       int tid)
{
#pragma unroll
    for (int k = 0; k < 16; k++) {
        int e = tid + (k << 8);
        int row = e >> 5, c16 = e & 31;
        uint4 v = reinterpret_cast<const uint4*>(src + (size_t)row * C1)[c16];
        uint32_t off = ((uint32_t)row << 9) | (uint32_t)((c16 ^ (row & 7)) << 4);
        *reinterpret_cast<uint4*>(dst + off) = v;
    }
}
__device__ __forceinline__ void fill_p(char* dst, const __nv_bfloat16* __restrict__ src,
                                       int tid)
{
#pragma unroll
    for (int k = 0; k < 8; k++) {
        int e = tid + (k << 8);
        int row = e >> 5, c16 = e & 31;
        uint4 v = reinterpret_cast<const uint4*>(src + (size_t)row * C1)[c16];
        uint32_t off = ((uint32_t)row << 9) | (uint32_t)((c16 ^ (row & 7)) << 4);
        *reinterpret_cast<uint4*>(dst + off) = v;
    }
}

__device__ __forceinline__ void ins4(float (&bk)[4], int (&bi)[4],
                                     float& worst, float v, int j)
{
    bool done = false;
#pragma unroll
    for (int s = 0; s < 4; s++)
        if (!done && bk[s] == worst) { bk[s] = v; bi[s] = j; done = true; }
    worst = fmaxf(fmaxf(bk[0], bk[1]), fmaxf(bk[2], bk[3]));
}

__device__ __forceinline__ void ins8(float (&bk)[SHORT], int (&bi)[SHORT],
                                     float& worst, float v, int j)
{
    if (v < worst) {
        bool done = false;
#pragma unroll
        for (int s = 0; s < SHORT; s++)
            if (!done && bk[s] == worst) { bk[s] = v; bi[s] = j; done = true; }
        worst = bk[0];
#pragma unroll
        for (int s = 1; s < SHORT; s++) worst = fmaxf(worst, bk[s]);
    }
}

__global__ void GRAM_BOUNDS gram_topk(
    const __nv_bfloat16* __restrict__ Qb, const __nv_bfloat16* __restrict__ Pb,
    const float* __restrict__ pn, int* __restrict__ si)
{
    extern __shared__ char sm[];
    char*  qs  = sm + SMQ;
    char*  ps  = sm + SMP;
    float* pns = (float*)(sm + SMPN);

    const int tid  = threadIdx.x;
    const int lane = tid & 31;
    const int wid  = tid >> 5;
    const int q0    = blockIdx.x * 128;
    const int pbase = blockIdx.y * (NP / GSPLIT);

    fill_q(qs, Qb + (size_t)q0 * C1, tid);

    const uint32_t qsb = s2u(qs), psb = s2u(ps);
    const int warp_q = (wid & 3) * 32;
    const int warp_p = (wid >> 2) * 32;
    const int r8 = lane & 7, mq = lane >> 3;
    const int achunk = mq >> 1, bchunk = mq & 1;

    uint32_t a_off[2]; int a_rx[2];
#pragma unroll
    for (int i = 0; i < 2; i++) {
        int row = warp_q + i * 16 + ((mq & 1) << 3) + r8;
        a_off[i] = qsb + ((uint32_t)row << 9);
        a_rx[i]  = row & 7;
    }
    uint32_t b_off[2]; int b_rx[2];
#pragma unroll
    for (int pr = 0; pr < 2; pr++) {
        int row = warp_p + (2 * pr + (mq >> 1)) * 8 + r8;
        b_off[pr] = psb + ((uint32_t)row << 9);
        b_rx[pr]  = row & 7;
    }

    float tk[4][4]; int ti[4][4]; float tw[4];
#pragma unroll
    for (int rc = 0; rc < 4; rc++) {
        tw[rc] = 3.0e38f;
#pragma unroll
        for (int s = 0; s < 4; s++) { tk[rc][s] = 3.0e38f; ti[rc][s] = 0; }
    }
    const int colb = warp_p + (lane & 3) * 2;

    for (int t = 0; t < TILES; t++) {
        const int p0 = pbase + t * PTILE;
        fill_p(ps, Pb + (size_t)p0 * C1, tid);
        if (tid < PTILE) pns[tid] = pn[p0 + tid];
        __syncthreads();

        float acc[2][4][4];
#pragma unroll
        for (int i = 0; i < 2; i++)
#pragma unroll
            for (int j = 0; j < 4; j++)
#pragma unroll
                for (int e = 0; e < 4; e++) acc[i][j][e] = 0.f;

#pragma unroll 4
        for (int s = 0; s < 16; s++) {
            uint32_t a[2][4];
            ldsm_x4(a[0], a_off[0] + (uint32_t)((((2 * s) + achunk) ^ a_rx[0]) << 4));
            ldsm_x4(a[1], a_off[1] + (uint32_t)((((2 * s) + achunk) ^ a_rx[1]) << 4));
            uint32_t b[4][2];
#pragma unroll
            for (int pr = 0; pr < 2; pr++) {
                uint32_t tr[4];
                ldsm_x4(tr, b_off[pr] + (uint32_t)((((2 * s) + bchunk) ^ b_rx[pr]) << 4));
                b[2 * pr][0]     = tr[0]; b[2 * pr][1]     = tr[1];
                b[2 * pr + 1][0] = tr[2]; b[2 * pr + 1][1] = tr[3];
            }
#pragma unroll
            for (int i = 0; i < 2; i++)
#pragma unroll
                for (int j = 0; j < 4; j++)
                    mma16816(acc[i][j], a[i], b[j]);
        }

#pragma unroll
        for (int i = 0; i < 2; i++) {
            const int rc0 = 2 * i, rc1 = 2 * i + 1;
#pragma unroll
            for (int j = 0; j < 4; j++) {
                const int col = colb + j * 8;
                const float2 pnv = *(const float2*)(pns + col);
                const float v00 = fmaf(-2.f, acc[i][j][0], pnv.x);
                const float v01 = fmaf(-2.f, acc[i][j][1], pnv.y);
                if (fminf(v00, v01) < tw[rc0]) {
                    if (v00 < tw[rc0]) ins4(tk[rc0], ti[rc0], tw[rc0], v00, p0 + col);
                    if (v01 < tw[rc0]) ins4(tk[rc0], ti[rc0], tw[rc0], v01, p0 + col + 1);
                }
                const float v10 = fmaf(-2.f, acc[i][j][2], pnv.x);
                const float v11 = fmaf(-2.f, acc[i][j][3], pnv.y);
                if (fminf(v10, v11) < tw[rc1]) {
                    if (v10 < tw[rc1]) ins4(tk[rc1], ti[rc1], tw[rc1], v10, p0 + col);
                    if (v11 < tw[rc1]) ins4(tk[rc1], ti[rc1], tw[rc1], v11, p0 + col + 1);
                }
            }
        }
        __syncthreads();
    }

    {
        float* mk = (float*)(sm + SMQ);
        int*   mi = (int*)(sm + SMQ);
        const int rowbase = warp_q + (lane >> 2);
        const int bin = ((wid >> 2) << 2) | (lane & 3);
#pragma unroll
        for (int rc = 0; rc < 4; rc++) {
            const int row = rowbase + rc * 8;
#pragma unroll
            for (int s = 0; s < 4; s++) {
                mk[row * 64 + bin * 8 + 2 * s]     = tk[rc][s];
                mi[row * 64 + bin * 8 + 2 * s + 1] = ti[rc][s];
            }
        }
        __syncthreads();
        if (tid < 128) {
            float fk[SHORT]; int fi[SHORT]; float w2 = 3.0e38f;
#pragma unroll
            for (int s = 0; s < SHORT; s++) { fk[s] = 3.0e38f; fi[s] = 0; }
#pragma unroll
            for (int u = 0; u < 32; u++) {
                float v = mk[tid * 64 + 2 * u];
                int  id = mi[tid * 64 + 2 * u + 1];
                ins8(fk, fi, w2, v, id);
            }
            const size_t ob = ((size_t)(q0 + tid) * GSPLIT + blockIdx.y) * SHORT;
#pragma unroll
            for (int s = 0; s < SHORT; s++) si[ob + s] = fi[s];
        }
    }
}

// ---------------------------------------------------------------------------
// exact fp32 rescore of 64 candidates/query -> top-5 + softmax(softplus)
// ---------------------------------------------------------------------------
__global__ __launch_bounds__(128) void rescore(
    const float* __restrict__ Qt, const float* __restrict__ Pt,
    const float* __restrict__ pn, const int* __restrict__ si,
    const float* __restrict__ a1, const float* __restrict__ a2,
    float* __restrict__ w, int* __restrict__ wi)
{
    const unsigned FULL = 0xffffffffu;
    const int lane = threadIdx.x & 31;
    const int q = blockIdx.x * 4 + (threadIdx.x >> 5);

    const float4* qr = (const float4*)(Qt + (size_t)q * C1);
    float4 qa = qr[lane * 2], qb = qr[lane * 2 + 1];

    int myc0 = si[(size_t)q * NCAND + lane];
    int myc1 = si[(size_t)q * NCAND + 32 + lane];
    float k0 = 3.0e38f, k1 = 3.0e38f;
    for (int c = 0; c < NCAND; c++) {
        const int src = c & 31;
        int j = __shfl_sync(FULL, (c < 32) ? myc0 : myc1, src);
        const float4* pr = (const float4*)(Pt + (size_t)j * C1);
        float4 pa = pr[lane * 2], pb = pr[lane * 2 + 1];
        float s = qa.x * pa.x;
        s = fmaf(qa.y, pa.y, s); s = fmaf(qa.z, pa.z, s); s = fmaf(qa.w, pa.w, s);
        s = fmaf(qb.x, pb.x, s); s = fmaf(qb.y, pb.y, s);
        s = fmaf(qb.z, pb.z, s); s = fmaf(qb.w, pb.w, s);
#pragma unroll
        for (int o = 16; o; o >>= 1) s += __shfl_xor_sync(FULL, s, o);
        if (lane == src) {
            float key = fmaf(-2.f, s, pn[j]);
            if (c < 32) k0 = key; else k1 = key;
        }
    }

    int ids[5];
#pragma unroll
    for (int r5 = 0; r5 < 5; r5++) {
        const int lsel = (k1 < k0) ? 1 : 0;
        float bv = lsel ? k1 : k0;
        int bl = lane;
#pragma unroll
        for (int o = 16; o; o >>= 1) {
            float ov = __shfl_xor_sync(FULL, bv, o);
            int   ol = __shfl_xor_sync(FULL, bl, o);
            if (ov < bv || (ov == bv && ol < bl)) { bv = ov; bl = ol; }
        }
        const int sel = __shfl_sync(FULL, lsel, bl);
        ids[r5] = __shfl_sync(FULL, sel ? myc1 : myc0, bl);
        if (lane == bl) { if (lsel) k1 = 3.0e38f; else k0 = 3.0e38f; }
    }

    if (lane == 0) {
        const float a1v = a1[q];
        float sc[5]; float m = -3.0e38f;
#pragma unroll
        for (int s = 0; s < 5; s++) {
            float x  = a1v + a2[ids[s]];
            float sp = fmaxf(x, 0.f) + log1pf(expf(-fabsf(x)));
            sc[s] = sp; m = fmaxf(m, sp);
        }
        float sum = 0.f;
#pragma unroll
        for (int s = 0; s < 5; s++) { sc[s] = expf(sc[s] - m); sum += sc[s]; }
        float inv = 1.f / sum;
#pragma unroll
        for (int s = 0; s < 5; s++) {
            w[(size_t)q * 5 + s]  = sc[s] * inv;
            wi[(size_t)q * 5 + s] = ids[s];
        }
    }
}

// ---------------------------------------------------------------------------
// MLP GEMM with fused per-block BN partial stats (sum, sumsq per feature)
// ---------------------------------------------------------------------------
__global__ __launch_bounds__(256) void mlp_gemm_s(
    const float* __restrict__ X, int N, int C, int cstride, int bstride,
    const float* __restrict__ W,
    const float* __restrict__ alpha, const float* __restrict__ shift,
    float* __restrict__ Z, float* __restrict__ ps, float* __restrict__ pq,
    int nblk)
{
    __shared__ float xs[32 * 64];
    __shared__ float ws[64 * 33];
    const int tid = threadIdx.x;
    const int n0  = blockIdx.x * 64;
    const int f0  = blockIdx.y * 64;
    const float* Xb = X + (size_t)(n0 >> 12) * bstride + (n0 & 4095);
    const int fl = tid & 63;
    const int nh = tid >> 6;

    float acc[16];
#pragma unroll
    for (int i = 0; i < 16; i++) acc[i] = 0.f;

    for (int c0 = 0; c0 < C; c0 += 32) {
#pragma unroll
        for (int k = 0; k < 8; k++) {
            int e  = tid + k * 256;
            int cc = e >> 6, nn = e & 63;
            float v = Xb[(size_t)(c0 + cc) * cstride + nn];
            if (alpha) v = fmaxf(fmaf(v, alpha[c0 + cc], shift[c0 + cc]), 0.f);
            xs[cc * 64 + nn] = v;
        }
#pragma unroll
        for (int k = 0; k < 8; k++) {
            int e  = tid + k * 256;
            int ff = e >> 5, cc = e & 31;
            ws[ff * 33 + cc] = W[(f0 + ff) * C + c0 + cc];
        }
        __syncthreads();
#pragma unroll
        for (int cc = 0; cc < 32; cc++) {
            float wv = ws[fl * 33 + cc];
            const float4* xr = (const float4*)&xs[cc * 64 + nh * 16];
#pragma unroll
            for (int v4 = 0; v4 < 4; v4++) {
                float4 x4 = xr[v4];
                acc[v4*4+0] = fmaf(wv, x4.x, acc[v4*4+0]);
                acc[v4*4+1] = fmaf(wv, x4.y, acc[v4*4+1]);
                acc[v4*4+2] = fmaf(wv, x4.z, acc[v4*4+2]);
                acc[v4*4+3] = fmaf(wv, x4.w, acc[v4*4+3]);
            }
        }
        __syncthreads();
    }
    float* Zo = Z + (size_t)(f0 + fl) * N + n0 + nh * 16;
#pragma unroll
    for (int v4 = 0; v4 < 4; v4++)
        ((float4*)Zo)[v4] = make_float4(acc[v4*4+0], acc[v4*4+1], acc[v4*4+2], acc[v4*4+3]);

    // fused BN partial stats: per feature, sum over this block's 64 n values
    float s = 0.f, q = 0.f;
#pragma unroll
    for (int i = 0; i < 16; i++) { s += acc[i]; q = fmaf(acc[i], acc[i], q); }
    __shared__ float rs[256], rq[256];
    rs[tid] = s; rq[tid] = q;
    __syncthreads();
    if (tid < 64) {
        float S = rs[tid] + rs[64 + tid] + rs[128 + tid] + rs[192 + tid];
        float Q = rq[tid] + rq[64 + tid] + rq[128 + tid] + rq[192 + tid];
        ps[(size_t)(f0 + tid) * nblk + blockIdx.x] = S;
        pq[(size_t)(f0 + tid) * nblk + blockIdx.x] = Q;
    }
}

// finalize BN: reduce nblk partials per feature -> alpha/shift
__global__ __launch_bounds__(256) void statsfin(
    const float* __restrict__ ps, const float* __restrict__ pq, int nblk, int N,
    const float* __restrict__ gamma, const float* __restrict__ beta,
    float* __restrict__ alpha, float* __restrict__ shift)
{
    __shared__ float ss[256], sq[256];
    const int f = blockIdx.x, tid = threadIdx.x;
    float s = 0.f, q = 0.f;
    for (int i = tid; i < nblk; i += 256) {
        s += ps[(size_t)f * nblk + i];
        q += pq[(size_t)f * nblk + i];
    }
    ss[tid] = s; sq[tid] = q; __syncthreads();
    for (int st = 128; st > 0; st >>= 1) {
        if (tid < st) { ss[tid] += ss[tid + st]; sq[tid] += sq[tid + st]; }
        __syncthreads();
    }
    if (tid == 0) {
        float m   = ss[0] / (float)N;
        float var = sq[0] / (float)N - m * m;
        float a   = rsqrtf(var + 1e-5f) * gamma[f];
        alpha[f] = a;
        shift[f] = beta[f] - m * a;
    }
}

__global__ __launch_bounds__(256) void ascore(
    const float* __restrict__ Z2, int N,
    const float* __restrict__ alpha, const float* __restrict__ shift,
    const float* __restrict__ cw, const float* __restrict__ cb,
    float* __restrict__ a)
{
    const int n = blockIdx.x * 256 + threadIdx.x;
    float s = cb[0];
#pragma unroll 4
    for (int g = 0; g < F2; g++) {
        float v = fmaxf(fmaf(Z2[(size_t)g * N + n], alpha[g], shift[g]), 0.f);
        s = fmaf(v, cw[g], s);
    }
    a[n] = s;
}

__global__ __launch_bounds__(256) void copy_kernel(
    const float* __restrict__ src, float* __restrict__ dst)
{
    const int i = blockIdx.x * 256 + threadIdx.x;
    ((float4*)dst)[i] = ((const float4*)src)[i];
}

__global__ __launch_bounds__(256) void attn_out_kernel(
    const float* __restrict__ PS,
    const float* __restrict__ w, const int* __restrict__ wi,
    float* __restrict__ out)
{
    __shared__ float sw[QT * 5];
    __shared__ int   soff[QT * 5];
    const int tid = threadIdx.x;
    const int q0  = blockIdx.x * QT;
    for (int e = tid; e < QT * 5; e += 256) {
        int q = e / 5, k = e % 5;
        int idx = wi[(q0 + q) * 5 + k];
        soff[e] = (idx >> 12) * (C1 * HW) + (idx & 4095);
        sw[e]   = w[(q0 + q) * 5 + k];
    }
    __syncthreads();
    const int n   = tid & 63;
    const int cb0 = tid >> 6;
    float wv[5]; int ov[5];
#pragma unroll
    for (int k = 0; k < 5; k++) { wv[k] = sw[n * 5 + k]; ov[k] = soff[n * 5 + k]; }
    for (int c = cb0; c < C1; c += 4) {
        float s = 0.f;
#pragma unroll
        for (int k = 0; k < 5; k++) s = fmaf(wv[k], PS[ov[k] + (size_t)c * HW], s);
        out[(size_t)(C1 + c) * HW + q0 + n] = s;
    }
}

// ---------------------------------------------------------------------------
extern "C" void kernel_launch(void* const* d_in, const int* in_sizes, int n_in,
                              void* d_out, int out_size)
{
    (void)in_sizes; (void)n_in; (void)out_size;
    const float* inp_cont    = (const float*)d_in[0];
    const float* peers_cont  = (const float*)d_in[2];
    const float* peers_style = (const float*)d_in[3];
    const float* W1  = (const float*)d_in[4];
    const float* g1  = (const float*)d_in[6];
    const float* be1 = (const float*)d_in[7];
    const float* W2  = (const float*)d_in[8];
    const float* g2  = (const float*)d_in[10];
    const float* be2 = (const float*)d_in[11];
    const float* cw1 = (const float*)d_in[12];
    const float* cb1 = (const float*)d_in[13];
    const float* cw2 = (const float*)d_in[14];
    const float* cb2 = (const float*)d_in[15];
    float* out = (float*)d_out;

    float* sc = nullptr; int* isc = nullptr; __nv_bfloat16* bf = nullptr;
    cudaGetSymbolAddress((void**)&sc,  g_scratch);
    cudaGetSymbolAddress((void**)&isc, g_iscratch);
    cudaGetSymbolAddress((void**)&bf,  g_bf16);

    float* z1q  = sc + OFF_Z1Q;  float* z2q  = sc + OFF_Z2Q;
    float* z1p  = sc + OFF_Z1P;  float* z2p  = sc + OFF_Z2P;
    float* pn   = sc + OFF_PN;
    float* a1   = sc + OFF_A1;   float* a2   = sc + OFF_A2;
    float* al1q = sc + OFF_AL1Q; float* sh1q = sc + OFF_SH1Q;
    float* al2q = sc + OFF_AL2Q; float* sh2q = sc + OFF_SH2Q;
    float* al1p = sc + OFF_AL1P; float* sh1p = sc + OFF_SH1P;
    float* al2p = sc + OFF_AL2P; float* sh2p = sc + OFF_SH2P;
    float* Qt   = sc + OFF_QT;   float* Pt   = sc + OFF_PT;
    float* wb   = sc + OFF_W;
    float* psp  = sc + OFF_PSP;  float* pqp  = sc + OFF_PQP;
    float* psq  = sc + OFF_PSQ;  float* pqq  = sc + OFF_PQQ;
    __nv_bfloat16* Qb = bf;
    __nv_bfloat16* Pb = bf + (size_t)NQ * C1;
    int* sib = isc + IOFF_SI;    int* wib = isc + IOFF_WI;

    static cudaStream_t s1 = nullptr, s2 = nullptr;
    static cudaEvent_t  eFork = nullptr, eJ1 = nullptr, eJ2 = nullptr,
                        eQ = nullptr, ePN = nullptr;
    if (s1 == nullptr) {
        cudaStreamCreateWithFlags(&s1, cudaStreamNonBlocking);
        cudaStreamCreateWithFlags(&s2, cudaStreamNonBlocking);
        cudaEventCreateWithFlags(&eFork, cudaEventDisableTiming);
        cudaEventCreateWithFlags(&eJ1,   cudaEventDisableTiming);
        cudaEventCreateWithFlags(&eJ2,   cudaEventDisableTiming);
        cudaEventCreateWithFlags(&eQ,    cudaEventDisableTiming);
        cudaEventCreateWithFlags(&ePN,   cudaEventDisableTiming);
        cudaFuncSetAttribute(gram_topk,
                             cudaFuncAttributeMaxDynamicSharedMemorySize, SMTOT);
    }

    cudaEventRecord(eFork, 0);
    cudaStreamWaitEvent(s1, eFork, 0);
    cudaStreamWaitEvent(s2, eFork, 0);

    // ---- stream s1: pn direct, then peers MLP chain (fused stats) -> a2 ----
    pnormA<<<NP / 256, 256, 0, s1>>>(peers_cont, pn);
    cudaEventRecord(ePN, s1);
    mlp_gemm_s<<<dim3(NP / 64, F1 / 64), 256, 0, s1>>>(
        peers_cont, NP, C1, HW, C1 * HW, W1, nullptr, nullptr, z1p, psp, pqp, NP / 64);
    statsfin<<<F1, 256, 0, s1>>>(psp, pqp, NP / 64, NP, g1, be1, al1p, sh1p);
    mlp_gemm_s<<<dim3(NP / 64, F2 / 64), 256, 0, s1>>>(
        z1p, NP, F1, NP, HW, W2, al1p, sh1p, z2p, psp, pqp, NP / 64);
    statsfin<<<F2, 256, 0, s1>>>(psp, pqp, NP / 64, NP, g2, be2, al2p, sh2p);
    ascore<<<NP / 256, 256, 0, s1>>>(z2p, NP, al2p, sh2p, cw2, cb2, a2);
    cudaEventRecord(eJ1, s1);

    // ---- stream s2: Q transconv, query MLP chain (fused stats) -> a1, copy ----
    transconv<<<dim3(NQ / 32, C1 / 32), 256, 0, s2>>>(inp_cont, Qt, Qb);
    cudaEventRecord(eQ, s2);
    mlp_gemm_s<<<dim3(NQ / 64, F1 / 64), 256, 0, s2>>>(
        inp_cont, NQ, C1, HW, C1 * HW, W1, nullptr, nullptr, z1q, psq, pqq, NQ / 64);
    statsfin<<<F1, 256, 0, s2>>>(psq, pqq, NQ / 64, NQ, g1, be1, al1q, sh1q);
    mlp_gemm_s<<<dim3(NQ / 64, F2 / 64), 256, 0, s2>>>(
        z1q, NQ, F1, NQ, HW, W2, al1q, sh1q, z2q, psq, pqq, NQ / 64);
    statsfin<<<F2, 256, 0, s2>>>(psq, pqq, NQ / 64, NQ, g2, be2, al2q, sh2q);
    ascore<<<NQ / 256, 256, 0, s2>>>(z2q, NQ, al2q, sh2q, cw1, cb1, a1);
    copy_kernel<<<(C1 * HW / 4) / 256, 256, 0, s2>>>(inp_cont, out);
    cudaEventRecord(eJ2, s2);

    // ---- stream 0: P transconv -> gram (waits Qb + pn) ----
    transconv<<<dim3(NP / 32, C1 / 32), 256>>>(peers_cont, Pt, Pb);
    cudaStreamWaitEvent(0, eQ, 0);
    cudaStreamWaitEvent(0, ePN, 0);
    gram_topk<<<dim3(NQ / 128, GSPLIT), 256, SMTOT>>>(Qb, Pb, pn, sib);

    // ---- join, then exact rescore + attention output on stream 0 ----
    cudaStreamWaitEvent(0, eJ1, 0);
    cudaStreamWaitEvent(0, eJ2, 0);
    rescore<<<NQ / 4, 128>>>(Qt, Pt, pn, sib, a1, a2, wb, wib);
    attn_out_kernel<<<NQ / QT, 256>>>(peers_style, wb, wib, out);
}

// round 17
// speedup vs baseline: 1.0173x; 1.0173x over previous
#include <cuda_runtime.h>
#include <cuda_bf16.h>
#include <math.h>
#include <stdint.h>

// ---------------------------------------------------------------------------
// PeerRegularizationLayerAtt — mma.sync Gram (2 CTAs/SM, reg-capped) +
// multi-stream overlap, BN-stats-fused MLP split across both streams.
// N=4096 queries, M=16384 peers, C=Cs=256, K=5.
// ---------------------------------------------------------------------------

#define HW     4096
#define NQ     4096
#define NP     16384
#define C1     256
#define F1     128
#define F2     64
#define KNN    5
#define QT     64
#define GSPLIT 8
#define PTILE  64
#define TILES  ((NP / GSPLIT) / PTILE)   // 32
#define SHORT  8
#define NCAND  (GSPLIT * SHORT)          // 64
#define NPH    (NP / 2)                  // 8192 rows per half

#if defined(__CUDACC_VER_MAJOR__) && (__CUDACC_VER_MAJOR__ > 12 || \
    (__CUDACC_VER_MAJOR__ == 12 && __CUDACC_VER_MINOR__ >= 4))
#define GRAM_BOUNDS __maxnreg__(104)
#else
#define GRAM_BOUNDS __launch_bounds__(256, 2)
#endif

// ---------------- float scratch layout ----------------
constexpr size_t OFF_Z1Q  = 0;
constexpr size_t OFF_Z2Q  = OFF_Z1Q  + (size_t)F1 * NQ;
constexpr size_t OFF_Z1P  = OFF_Z2Q  + (size_t)F2 * NQ;
constexpr size_t OFF_Z2P  = OFF_Z1P  + (size_t)F1 * NP;
constexpr size_t OFF_PN   = OFF_Z2P  + (size_t)F2 * NP;
constexpr size_t OFF_A1   = OFF_PN   + NP;
constexpr size_t OFF_A2   = OFF_A1   + NQ;
constexpr size_t OFF_AL1Q = OFF_A2   + NP;
constexpr size_t OFF_SH1Q = OFF_AL1Q + F1;
constexpr size_t OFF_AL2Q = OFF_SH1Q + F1;
constexpr size_t OFF_SH2Q = OFF_AL2Q + F2;
constexpr size_t OFF_AL1P = OFF_SH2Q + F2;
constexpr size_t OFF_SH1P = OFF_AL1P + F1;
constexpr size_t OFF_AL2P = OFF_SH1P + F1;
constexpr size_t OFF_SH2P = OFF_AL2P + F2;
constexpr size_t OFF_QT   = OFF_SH2P + F2;
constexpr size_t OFF_PT   = OFF_QT   + (size_t)NQ * C1;
constexpr size_t OFF_W    = OFF_PT   + (size_t)NP * C1;
constexpr size_t OFF_PSP  = OFF_W    + (size_t)NQ * KNN;      // F1*256 partials (peers)
constexpr size_t OFF_PQP  = OFF_PSP  + (size_t)F1 * 256;
constexpr size_t OFF_PSQ  = OFF_PQP  + (size_t)F1 * 256;      // F1*64 (query)
constexpr size_t OFF_PQQ  = OFF_PSQ  + (size_t)F1 * 64;
constexpr size_t SCRATCH_FLOATS = OFF_PQQ + (size_t)F1 * 64;

constexpr size_t IOFF_SI  = 0;
constexpr size_t IOFF_WI  = (size_t)NQ * NCAND;
constexpr size_t SCRATCH_INTS = IOFF_WI + (size_t)NQ * KNN;

__device__ float g_scratch[SCRATCH_FLOATS];
__device__ int   g_iscratch[SCRATCH_INTS];
__device__ __nv_bfloat16 g_bf16[(size_t)(NQ + NP) * C1];

// ---------------- PTX helpers (arch-agnostic: ldmatrix + mma.sync) ----------
__device__ __forceinline__ uint32_t s2u(const void* p) {
    uint32_t a;
    asm("{ .reg .u64 t; cvta.to.shared.u64 t, %1; cvt.u32.u64 %0, t; }"
        : "=r"(a) : "l"(p));
    return a;
}
__device__ __forceinline__ void ldsm_x4(uint32_t* r, uint32_t addr) {
    asm volatile("ldmatrix.sync.aligned.m8n8.x4.shared.b16 {%0,%1,%2,%3}, [%4];"
        : "=r"(r[0]), "=r"(r[1]), "=r"(r[2]), "=r"(r[3]) : "r"(addr));
}
__device__ __forceinline__ void mma16816(float* d, const uint32_t* a,
                                         const uint32_t* b) {
    asm volatile(
        "mma.sync.aligned.m16n8k16.row.col.f32.bf16.bf16.f32 "
        "{%0,%1,%2,%3}, {%4,%5,%6,%7}, {%8,%9}, {%0,%1,%2,%3};"
        : "+f"(d[0]), "+f"(d[1]), "+f"(d[2]), "+f"(d[3])
        : "r"(a[0]), "r"(a[1]), "r"(a[2]), "r"(a[3]), "r"(b[0]), "r"(b[1]));
}

// ---------------------------------------------------------------------------
// transpose+convert: X [B][C][HW] fp32 -> Xt [n][c] fp32, Xb [n][c] bf16
// ---------------------------------------------------------------------------
__global__ __launch_bounds__(256) void transconv(
    const float* __restrict__ X, float* __restrict__ Xt, __nv_bfloat16* __restrict__ Xb)
{
    __shared__ float t[32][33];
    const int n0 = blockIdx.x * 32, c0 = blockIdx.y * 32;
    const int tx = threadIdx.x & 31, ty = threadIdx.x >> 5;
    const float* base = X + (size_t)(n0 >> 12) * (C1 * HW) + (n0 & 4095);
#pragma unroll
    for (int i = 0; i < 4; i++) {
        int cc = ty + i * 8;
        t[cc][tx] = base[(size_t)(c0 + cc) * HW + tx];
    }
    __syncthreads();
#pragma unroll
    for (int i = 0; i < 4; i++) {
        int r = ty + i * 8;
        float v = t[tx][r];
        size_t o = (size_t)(n0 + r) * C1 + c0 + tx;
        Xt[o] = v;
        Xb[o] = __float2bfloat16(v);
    }
}

// exact fp32 peer squared norms straight from [B][C][HW] layout (coalesced)
__global__ __launch_bounds__(256) void pnormA(
    const float* __restrict__ PC, float* __restrict__ pn)
{
    const int j = blockIdx.x * 256 + threadIdx.x;
    const float* base = PC + (size_t)(j >> 12) * (C1 * HW) + (j & 4095);
    float s = 0.f;
#pragma unroll 8
    for (int c = 0; c < C1; c++) { float v = base[(size_t)c * HW]; s = fmaf(v, v, s); }
    pn[j] = s;
}

// ---------------------------------------------------------------------------
// mma.sync Gram + per-thread-per-row top-4 (registers) -> top-8/split
// ---------------------------------------------------------------------------
#define SMQ   0
#define SMP   65536
#define SMPN  98304
#define SMTOT (SMPN + 256)

__device__ __forceinline__ void fill_q(char* dst, const __nv_bfloat16* __restrict__ src,
                                       int tid)
{
#pragma unroll
    for (int k = 0; k < 16; k++) {
        int e = tid + (k << 8);
        int row = e >> 5, c16 = e & 31;
        uint4 v = reinterpret_cast<const uint4*>(src + (size_t)row * C1)[c16];
        uint32_t off = ((uint32_t)row << 9) | (uint32_t)((c16 ^ (row & 7)) << 4);
        *reinterpret_cast<uint4*>(dst + off) = v;
    }
}
__device__ __forceinline__ void fill_p(char* dst, const __nv_bfloat16* __restrict__ src,
                                       int tid)
{
#pragma unroll
    for (int k = 0; k < 8; k++) {
        int e = tid + (k << 8);
        int row = e >> 5, c16 = e & 31;
        uint4 v = reinterpret_cast<const uint4*>(src + (size_t)row * C1)[c16];
        uint32_t off = ((uint32_t)row << 9) | (uint32_t)((c16 ^ (row & 7)) << 4);
        *reinterpret_cast<uint4*>(dst + off) = v;
    }
}

__device__ __forceinline__ void ins4(float (&bk)[4], int (&bi)[4],
                                     float& worst, float v, int j)
{
    bool done = false;
#pragma unroll
    for (int s = 0; s < 4; s++)
        if (!done && bk[s] == worst) { bk[s] = v; bi[s] = j; done = true; }
    worst = fmaxf(fmaxf(bk[0], bk[1]), fmaxf(bk[2], bk[3]));
}

__device__ __forceinline__ void ins8(float (&bk)[SHORT], int (&bi)[SHORT],
                                     float& worst, float v, int j)
{
    if (v < worst) {
        bool done = false;
#pragma unroll
        for (int s = 0; s < SHORT; s++)
            if (!done && bk[s] == worst) { bk[s] = v; bi[s] = j; done = true; }
        worst = bk[0];
#pragma unroll
        for (int s = 1; s < SHORT; s++) worst = fmaxf(worst, bk[s]);
    }
}

__global__ void GRAM_BOUNDS gram_topk(
    const __nv_bfloat16* __restrict__ Qb, const __nv_bfloat16* __restrict__ Pb,
    const float* __restrict__ pn, int* __restrict__ si)
{
    extern __shared__ char sm[];
    char*  qs  = sm + SMQ;
    char*  ps  = sm + SMP;
    float* pns = (float*)(sm + SMPN);

    const int tid  = threadIdx.x;
    const int lane = tid & 31;
    const int wid  = tid >> 5;
    const int q0    = blockIdx.x * 128;
    const int pbase = blockIdx.y * (NP / GSPLIT);

    fill_q(qs, Qb + (size_t)q0 * C1, tid);

    const uint32_t qsb = s2u(qs), psb = s2u(ps);
    const int warp_q = (wid & 3) * 32;
    const int warp_p = (wid >> 2) * 32;
    const int r8 = lane & 7, mq = lane >> 3;
    const int achunk = mq >> 1, bchunk = mq & 1;

    uint32_t a_off[2]; int a_rx[2];
#pragma unroll
    for (int i = 0; i < 2; i++) {
        int row = warp_q + i * 16 + ((mq & 1) << 3) + r8;
        a_off[i] = qsb + ((uint32_t)row << 9);
        a_rx[i]  = row & 7;
    }
    uint32_t b_off[2]; int b_rx[2];
#pragma unroll
    for (int pr = 0; pr < 2; pr++) {
        int row = warp_p + (2 * pr + (mq >> 1)) * 8 + r8;
        b_off[pr] = psb + ((uint32_t)row << 9);
        b_rx[pr]  = row & 7;
    }

    float tk[4][4]; int ti[4][4]; float tw[4];
#pragma unroll
    for (int rc = 0; rc < 4; rc++) {
        tw[rc] = 3.0e38f;
#pragma unroll
        for (int s = 0; s < 4; s++) { tk[rc][s] = 3.0e38f; ti[rc][s] = 0; }
    }
    const int colb = warp_p + (lane & 3) * 2;

    for (int t = 0; t < TILES; t++) {
        const int p0 = pbase + t * PTILE;
        fill_p(ps, Pb + (size_t)p0 * C1, tid);
        if (tid < PTILE) pns[tid] = pn[p0 + tid];
        __syncthreads();

        float acc[2][4][4];
#pragma unroll
        for (int i = 0; i < 2; i++)
#pragma unroll
            for (int j = 0; j < 4; j++)
#pragma unroll
                for (int e = 0; e < 4; e++) acc[i][j][e] = 0.f;

#pragma unroll 4
        for (int s = 0; s < 16; s++) {
            uint32_t a[2][4];
            ldsm_x4(a[0], a_off[0] + (uint32_t)((((2 * s) + achunk) ^ a_rx[0]) << 4));
            ldsm_x4(a[1], a_off[1] + (uint32_t)((((2 * s) + achunk) ^ a_rx[1]) << 4));
            uint32_t b[4][2];
#pragma unroll
            for (int pr = 0; pr < 2; pr++) {
                uint32_t tr[4];
                ldsm_x4(tr, b_off[pr] + (uint32_t)((((2 * s) + bchunk) ^ b_rx[pr]) << 4));
                b[2 * pr][0]     = tr[0]; b[2 * pr][1]     = tr[1];
                b[2 * pr + 1][0] = tr[2]; b[2 * pr + 1][1] = tr[3];
            }
#pragma unroll
            for (int i = 0; i < 2; i++)
#pragma unroll
                for (int j = 0; j < 4; j++)
                    mma16816(acc[i][j], a[i], b[j]);
        }

#pragma unroll
        for (int i = 0; i < 2; i++) {
            const int rc0 = 2 * i, rc1 = 2 * i + 1;
#pragma unroll
            for (int j = 0; j < 4; j++) {
                const int col = colb + j * 8;
                const float2 pnv = *(const float2*)(pns + col);
                const float v00 = fmaf(-2.f, acc[i][j][0], pnv.x);
                const float v01 = fmaf(-2.f, acc[i][j][1], pnv.y);
                if (fminf(v00, v01) < tw[rc0]) {
                    if (v00 < tw[rc0]) ins4(tk[rc0], ti[rc0], tw[rc0], v00, p0 + col);
                    if (v01 < tw[rc0]) ins4(tk[rc0], ti[rc0], tw[rc0], v01, p0 + col + 1);
                }
                const float v10 = fmaf(-2.f, acc[i][j][2], pnv.x);
                const float v11 = fmaf(-2.f, acc[i][j][3], pnv.y);
                if (fminf(v10, v11) < tw[rc1]) {
                    if (v10 < tw[rc1]) ins4(tk[rc1], ti[rc1], tw[rc1], v10, p0 + col);
                    if (v11 < tw[rc1]) ins4(tk[rc1], ti[rc1], tw[rc1], v11, p0 + col + 1);
                }
            }
        }
        __syncthreads();
    }

    {
        float* mk = (float*)(sm + SMQ);
        int*   mi = (int*)(sm + SMQ);
        const int rowbase = warp_q + (lane >> 2);
        const int bin = ((wid >> 2) << 2) | (lane & 3);
#pragma unroll
        for (int rc = 0; rc < 4; rc++) {
            const int row = rowbase + rc * 8;
#pragma unroll
            for (int s = 0; s < 4; s++) {
                mk[row * 64 + bin * 8 + 2 * s]     = tk[rc][s];
                mi[row * 64 + bin * 8 + 2 * s + 1] = ti[rc][s];
            }
        }
        __syncthreads();
        if (tid < 128) {
            float fk[SHORT]; int fi[SHORT]; float w2 = 3.0e38f;
#pragma unroll
            for (int s = 0; s < SHORT; s++) { fk[s] = 3.0e38f; fi[s] = 0; }
#pragma unroll
            for (int u = 0; u < 32; u++) {
                float v = mk[tid * 64 + 2 * u];
                int  id = mi[tid * 64 + 2 * u + 1];
                ins8(fk, fi, w2, v, id);
            }
            const size_t ob = ((size_t)(q0 + tid) * GSPLIT + blockIdx.y) * SHORT;
#pragma unroll
            for (int s = 0; s < SHORT; s++) si[ob + s] = fi[s];
        }
    }
}

// ---------------------------------------------------------------------------
// exact fp32 rescore of 64 candidates/query -> top-5 + softmax(softplus)
// ---------------------------------------------------------------------------
__global__ __launch_bounds__(128) void rescore(
    const float* __restrict__ Qt, const float* __restrict__ Pt,
    const float* __restrict__ pn, const int* __restrict__ si,
    const float* __restrict__ a1, const float* __restrict__ a2,
    float* __restrict__ w, int* __restrict__ wi)
{
    const unsigned FULL = 0xffffffffu;
    const int lane = threadIdx.x & 31;
    const int q = blockIdx.x * 4 + (threadIdx.x >> 5);

    const float4* qr = (const float4*)(Qt + (size_t)q * C1);
    float4 qa = qr[lane * 2], qb = qr[lane * 2 + 1];

    int myc0 = si[(size_t)q * NCAND + lane];
    int myc1 = si[(size_t)q * NCAND + 32 + lane];
    float k0 = 3.0e38f, k1 = 3.0e38f;
    for (int c = 0; c < NCAND; c++) {
        const int src = c & 31;
        int j = __shfl_sync(FULL, (c < 32) ? myc0 : myc1, src);
        const float4* pr = (const float4*)(Pt + (size_t)j * C1);
        float4 pa = pr[lane * 2], pb = pr[lane * 2 + 1];
        float s = qa.x * pa.x;
        s = fmaf(qa.y, pa.y, s); s = fmaf(qa.z, pa.z, s); s = fmaf(qa.w, pa.w, s);
        s = fmaf(qb.x, pb.x, s); s = fmaf(qb.y, pb.y, s);
        s = fmaf(qb.z, pb.z, s); s = fmaf(qb.w, pb.w, s);
#pragma unroll
        for (int o = 16; o; o >>= 1) s += __shfl_xor_sync(FULL, s, o);
        if (lane == src) {
            float key = fmaf(-2.f, s, pn[j]);
            if (c < 32) k0 = key; else k1 = key;
        }
    }

    int ids[5];
#pragma unroll
    for (int r5 = 0; r5 < 5; r5++) {
        const int lsel = (k1 < k0) ? 1 : 0;
        float bv = lsel ? k1 : k0;
        int bl = lane;
#pragma unroll
        for (int o = 16; o; o >>= 1) {
            float ov = __shfl_xor_sync(FULL, bv, o);
            int   ol = __shfl_xor_sync(FULL, bl, o);
            if (ov < bv || (ov == bv && ol < bl)) { bv = ov; bl = ol; }
        }
        const int sel = __shfl_sync(FULL, lsel, bl);
        ids[r5] = __shfl_sync(FULL, sel ? myc1 : myc0, bl);
        if (lane == bl) { if (lsel) k1 = 3.0e38f; else k0 = 3.0e38f; }
    }

    if (lane == 0) {
        const float a1v = a1[q];
        float sc[5]; float m = -3.0e38f;
#pragma unroll
        for (int s = 0; s < 5; s++) {
            float x  = a1v + a2[ids[s]];
            float sp = fmaxf(x, 0.f) + log1pf(expf(-fabsf(x)));
            sc[s] = sp; m = fmaxf(m, sp);
        }
        float sum = 0.f;
#pragma unroll
        for (int s = 0; s < 5; s++) { sc[s] = expf(sc[s] - m); sum += sc[s]; }
        float inv = 1.f / sum;
#pragma unroll
        for (int s = 0; s < 5; s++) {
            w[(size_t)q * 5 + s]  = sc[s] * inv;
            wi[(size_t)q * 5 + s] = ids[s];
        }
    }
}

// ---------------------------------------------------------------------------
// MLP GEMM with fused per-block BN partial stats; boff = x-block offset
// ---------------------------------------------------------------------------
__global__ __launch_bounds__(256) void mlp_gemm_s(
    const float* __restrict__ X, int N, int C, int cstride, int bstride,
    const float* __restrict__ W,
    const float* __restrict__ alpha, const float* __restrict__ shift,
    float* __restrict__ Z, float* __restrict__ ps, float* __restrict__ pq,
    int nblk, int boff)
{
    __shared__ float xs[32 * 64];
    __shared__ float ws[64 * 33];
    const int tid = threadIdx.x;
    const int bx  = blockIdx.x + boff;
    const int n0  = bx * 64;
    const int f0  = blockIdx.y * 64;
    const float* Xb = X + (size_t)(n0 >> 12) * bstride + (n0 & 4095);
    const int fl = tid & 63;
    const int nh = tid >> 6;

    float acc[16];
#pragma unroll
    for (int i = 0; i < 16; i++) acc[i] = 0.f;

    for (int c0 = 0; c0 < C; c0 += 32) {
#pragma unroll
        for (int k = 0; k < 8; k++) {
            int e  = tid + k * 256;
            int cc = e >> 6, nn = e & 63;
            float v = Xb[(size_t)(c0 + cc) * cstride + nn];
            if (alpha) v = fmaxf(fmaf(v, alpha[c0 + cc], shift[c0 + cc]), 0.f);
            xs[cc * 64 + nn] = v;
        }
#pragma unroll
        for (int k = 0; k < 8; k++) {
            int e  = tid + k * 256;
            int ff = e >> 5, cc = e & 31;
            ws[ff * 33 + cc] = W[(f0 + ff) * C + c0 + cc];
        }
        __syncthreads();
#pragma unroll
        for (int cc = 0; cc < 32; cc++) {
            float wv = ws[fl * 33 + cc];
            const float4* xr = (const float4*)&xs[cc * 64 + nh * 16];
#pragma unroll
            for (int v4 = 0; v4 < 4; v4++) {
                float4 x4 = xr[v4];
                acc[v4*4+0] = fmaf(wv, x4.x, acc[v4*4+0]);
                acc[v4*4+1] = fmaf(wv, x4.y, acc[v4*4+1]);
                acc[v4*4+2] = fmaf(wv, x4.z, acc[v4*4+2]);
                acc[v4*4+3] = fmaf(wv, x4.w, acc[v4*4+3]);
            }
        }
        __syncthreads();
    }
    float* Zo = Z + (size_t)(f0 + fl) * N + n0 + nh * 16;
#pragma unroll
    for (int v4 = 0; v4 < 4; v4++)
        ((float4*)Zo)[v4] = make_float4(acc[v4*4+0], acc[v4*4+1], acc[v4*4+2], acc[v4*4+3]);

    float s = 0.f, q = 0.f;
#pragma unroll
    for (int i = 0; i < 16; i++) { s += acc[i]; q = fmaf(acc[i], acc[i], q); }
    __shared__ float rs[256], rq[256];
    rs[tid] = s; rq[tid] = q;
    __syncthreads();
    if (tid < 64) {
        float S = rs[tid] + rs[64 + tid] + rs[128 + tid] + rs[192 + tid];
        float Q = rq[tid] + rq[64 + tid] + rq[128 + tid] + rq[192 + tid];
        ps[(size_t)(f0 + tid) * nblk + bx] = S;
        pq[(size_t)(f0 + tid) * nblk + bx] = Q;
    }
}

// finalize BN: reduce nblk partials per feature -> alpha/shift
__global__ __launch_bounds__(256) void statsfin(
    const float* __restrict__ ps, const float* __restrict__ pq, int nblk, int N,
    const float* __restrict__ gamma, const float* __restrict__ beta,
    float* __restrict__ alpha, float* __restrict__ shift)
{
    __shared__ float ss[256], sq[256];
    const int f = blockIdx.x, tid = threadIdx.x;
    float s = 0.f, q = 0.f;
    for (int i = tid; i < nblk; i += 256) {
        s += ps[(size_t)f * nblk + i];
        q += pq[(size_t)f * nblk + i];
    }
    ss[tid] = s; sq[tid] = q; __syncthreads();
    for (int st = 128; st > 0; st >>= 1) {
        if (tid < st) { ss[tid] += ss[tid + st]; sq[tid] += sq[tid + st]; }
        __syncthreads();
    }
    if (tid == 0) {
        float m   = ss[0] / (float)N;
        float var = sq[0] / (float)N - m * m;
        float a   = rsqrtf(var + 1e-5f) * gamma[f];
        alpha[f] = a;
        shift[f] = beta[f] - m * a;
    }
}

__global__ __launch_bounds__(256) void ascore(
    const float* __restrict__ Z2, int N,
    const float* __restrict__ alpha, const float* __restrict__ shift,
    const float* __restrict__ cw, const float* __restrict__ cb,
    float* __restrict__ a)
{
    const int n = blockIdx.x * 256 + threadIdx.x;
    float s = cb[0];
#pragma unroll 4
    for (int g = 0; g < F2; g++) {
        float v = fmaxf(fmaf(Z2[(size_t)g * N + n], alpha[g], shift[g]), 0.f);
        s = fmaf(v, cw[g], s);
    }
    a[n] = s;
}

__global__ __launch_bounds__(256) void copy_kernel(
    const float* __restrict__ src, float* __restrict__ dst)
{
    const int i = blockIdx.x * 256 + threadIdx.x;
    ((float4*)dst)[i] = ((const float4*)src)[i];
}

__global__ __launch_bounds__(256) void attn_out_kernel(
    const float* __restrict__ PS,
    const float* __restrict__ w, const int* __restrict__ wi,
    float* __restrict__ out)
{
    __shared__ float sw[QT * 5];
    __shared__ int   soff[QT * 5];
    const int tid = threadIdx.x;
    const int q0  = blockIdx.x * QT;
    for (int e = tid; e < QT * 5; e += 256) {
        int q = e / 5, k = e % 5;
        int idx = wi[(q0 + q) * 5 + k];
        soff[e] = (idx >> 12) * (C1 * HW) + (idx & 4095);
        sw[e]   = w[(q0 + q) * 5 + k];
    }
    __syncthreads();
    const int n   = tid & 63;
    const int cb0 = tid >> 6;
    float wv[5]; int ov[5];
#pragma unroll
    for (int k = 0; k < 5; k++) { wv[k] = sw[n * 5 + k]; ov[k] = soff[n * 5 + k]; }
    for (int c = cb0; c < C1; c += 4) {
        float s = 0.f;
#pragma unroll
        for (int k = 0; k < 5; k++) s = fmaf(wv[k], PS[ov[k] + (size_t)c * HW], s);
        out[(size_t)(C1 + c) * HW + q0 + n] = s;
    }
}

// ---------------------------------------------------------------------------
extern "C" void kernel_launch(void* const* d_in, const int* in_sizes, int n_in,
                              void* d_out, int out_size)
{
    (void)in_sizes; (void)n_in; (void)out_size;
    const float* inp_cont    = (const float*)d_in[0];
    const float* peers_cont  = (const float*)d_in[2];
    const float* peers_style = (const float*)d_in[3];
    const float* W1  = (const float*)d_in[4];
    const float* g1  = (const float*)d_in[6];
    const float* be1 = (const float*)d_in[7];
    const float* W2  = (const float*)d_in[8];
    const float* g2  = (const float*)d_in[10];
    const float* be2 = (const float*)d_in[11];
    const float* cw1 = (const float*)d_in[12];
    const float* cb1 = (const float*)d_in[13];
    const float* cw2 = (const float*)d_in[14];
    const float* cb2 = (const float*)d_in[15];
    float* out = (float*)d_out;

    float* sc = nullptr; int* isc = nullptr; __nv_bfloat16* bf = nullptr;
    cudaGetSymbolAddress((void**)&sc,  g_scratch);
    cudaGetSymbolAddress((void**)&isc, g_iscratch);
    cudaGetSymbolAddress((void**)&bf,  g_bf16);

    float* z1q  = sc + OFF_Z1Q;  float* z2q  = sc + OFF_Z2Q;
    float* z1p  = sc + OFF_Z1P;  float* z2p  = sc + OFF_Z2P;
    float* pn   = sc + OFF_PN;
    float* a1   = sc + OFF_A1;   float* a2   = sc + OFF_A2;
    float* al1q = sc + OFF_AL1Q; float* sh1q = sc + OFF_SH1Q;
    float* al2q = sc + OFF_AL2Q; float* sh2q = sc + OFF_SH2Q;
    float* al1p = sc + OFF_AL1P; float* sh1p = sc + OFF_SH1P;
    float* al2p = sc + OFF_AL2P; float* sh2p = sc + OFF_SH2P;
    float* Qt   = sc + OFF_QT;   float* Pt   = sc + OFF_PT;
    float* wb   = sc + OFF_W;
    float* psp  = sc + OFF_PSP;  float* pqp  = sc + OFF_PQP;
    float* psq  = sc + OFF_PSQ;  float* pqq  = sc + OFF_PQQ;
    __nv_bfloat16* Qb = bf;
    __nv_bfloat16* Pb = bf + (size_t)NQ * C1;
    int* sib = isc + IOFF_SI;    int* wib = isc + IOFF_WI;

    static cudaStream_t s1 = nullptr, s2 = nullptr;
    static cudaEvent_t  eFork = nullptr, eJ1 = nullptr, eJ2 = nullptr,
                        eQ = nullptr, ePN = nullptr,
                        eH1 = nullptr, eH2 = nullptr, eS1 = nullptr, eS2 = nullptr;
    if (s1 == nullptr) {
        cudaStreamCreateWithFlags(&s1, cudaStreamNonBlocking);
        cudaStreamCreateWithFlags(&s2, cudaStreamNonBlocking);
        cudaEventCreateWithFlags(&eFork, cudaEventDisableTiming);
        cudaEventCreateWithFlags(&eJ1,   cudaEventDisableTiming);
        cudaEventCreateWithFlags(&eJ2,   cudaEventDisableTiming);
        cudaEventCreateWithFlags(&eQ,    cudaEventDisableTiming);
        cudaEventCreateWithFlags(&ePN,   cudaEventDisableTiming);
        cudaEventCreateWithFlags(&eH1,   cudaEventDisableTiming);
        cudaEventCreateWithFlags(&eH2,   cudaEventDisableTiming);
        cudaEventCreateWithFlags(&eS1,   cudaEventDisableTiming);
        cudaEventCreateWithFlags(&eS2,   cudaEventDisableTiming);
        cudaFuncSetAttribute(gram_topk,
                             cudaFuncAttributeMaxDynamicSharedMemorySize, SMTOT);
    }

    const int NBP = NP / 64;   // 256 x-blocks total for peers GEMMs
    const int HBP = NBP / 2;   // 128 per half

    cudaEventRecord(eFork, 0);
    cudaStreamWaitEvent(s1, eFork, 0);
    cudaStreamWaitEvent(s2, eFork, 0);

    // ---- s1: pn, then peers layer-1 half0 ----
    pnormA<<<NP / 256, 256, 0, s1>>>(peers_cont, pn);
    cudaEventRecord(ePN, s1);
    mlp_gemm_s<<<dim3(HBP, F1 / 64), 256, 0, s1>>>(
        peers_cont, NP, C1, HW, C1 * HW, W1, nullptr, nullptr, z1p, psp, pqp, NBP, 0);

    // ---- s2: Q transconv (gram dep), query layer-1, peers layer-1 half1 ----
    transconv<<<dim3(NQ / 32, C1 / 32), 256, 0, s2>>>(inp_cont, Qt, Qb);
    cudaEventRecord(eQ, s2);
    mlp_gemm_s<<<dim3(NQ / 64, F1 / 64), 256, 0, s2>>>(
        inp_cont, NQ, C1, HW, C1 * HW, W1, nullptr, nullptr, z1q, psq, pqq, NQ / 64, 0);
    statsfin<<<F1, 256, 0, s2>>>(psq, pqq, NQ / 64, NQ, g1, be1, al1q, sh1q);
    mlp_gemm_s<<<dim3(HBP, F1 / 64), 256, 0, s2>>>(
        peers_cont, NP, C1, HW, C1 * HW, W1, nullptr, nullptr, z1p, psp, pqp, NBP, HBP);
    cudaEventRecord(eH1, s2);

    // ---- s1: peers BN1 (waits half1), layer-2 half0 ----
    cudaStreamWaitEvent(s1, eH1, 0);
    statsfin<<<F1, 256, 0, s1>>>(psp, pqp, NBP, NP, g1, be1, al1p, sh1p);
    cudaEventRecord(eS1, s1);
    mlp_gemm_s<<<dim3(HBP, F2 / 64), 256, 0, s1>>>(
        z1p, NP, F1, NP, HW, W2, al1p, sh1p, z2p, psp, pqp, NBP, 0);

    // ---- s2: query layer-2 + ascore + copy; peers layer-2 half1 ----
    mlp_gemm_s<<<dim3(NQ / 64, F2 / 64), 256, 0, s2>>>(
        z1q, NQ, F1, NQ, HW, W2, al1q, sh1q, z2q, psq, pqq, NQ / 64, 0);
    statsfin<<<F2, 256, 0, s2>>>(psq, pqq, NQ / 64, NQ, g2, be2, al2q, sh2q);
    ascore<<<NQ / 256, 256, 0, s2>>>(z2q, NQ, al2q, sh2q, cw1, cb1, a1);
    copy_kernel<<<(C1 * HW / 4) / 256, 256, 0, s2>>>(inp_cont, out);
    cudaStreamWaitEvent(s2, eS1, 0);
    mlp_gemm_s<<<dim3(HBP, F2 / 64), 256, 0, s2>>>(
        z1p, NP, F1, NP, HW, W2, al1p, sh1p, z2p, psp, pqp, NBP, HBP);
    cudaEventRecord(eH2, s2);

    // ---- s1: peers BN2 (waits half1), ascore halves split across streams ----
    cudaStreamWaitEvent(s1, eH2, 0);
    statsfin<<<F2, 256, 0, s1>>>(psp, pqp, NBP, NP, g2, be2, al2p, sh2p);
    cudaEventRecord(eS2, s1);
    ascore<<<NPH / 256, 256, 0, s1>>>(z2p, NP, al2p, sh2p, cw2, cb2, a2);
    cudaEventRecord(eJ1, s1);
    cudaStreamWaitEvent(s2, eS2, 0);
    ascore<<<NPH / 256, 256, 0, s2>>>(z2p + NPH, NP, al2p, sh2p, cw2, cb2, a2 + NPH);
    cudaEventRecord(eJ2, s2);

    // ---- stream 0: P transconv -> gram (waits Qb + pn) ----
    transconv<<<dim3(NP / 32, C1 / 32), 256>>>(peers_cont, Pt, Pb);
    cudaStreamWaitEvent(0, eQ, 0);
    cudaStreamWaitEvent(0, ePN, 0);
    gram_topk<<<dim3(NQ / 128, GSPLIT), 256, SMTOT>>>(Qb, Pb, pn, sib);

    // ---- join, then exact rescore + attention output on stream 0 ----
    cudaStreamWaitEvent(0, eJ1, 0);
    cudaStreamWaitEvent(0, eJ2, 0);
    rescore<<<NQ / 4, 128>>>(Qt, Pt, pn, sib, a1, a2, wb, wib);
    attn_out_kernel<<<NQ / QT, 256>>>(peers_style, wb, wib, out);
}